// round 9
// baseline (speedup 1.0000x reference)
#include <cuda_runtime.h>
#include <cstdint>

// Problem constants (fixed by the dataset)
#define BQ    128
#define TT    512
#define CC    1024
#define LL    64
#define SS    129           // 2*LL + 1 extended states
#define BLANKC 1023
#define EPSF  1e-7f
#define JPER  5             // states per lane (26 lanes * 5 = 130 >= 129)
#define DEPTH 64            // smem ring rows (power of two)
#define RSTRIDE 68          // ring row stride in floats (66 used)
#define EF_TARGET 226       // rescale anchor: warp max near 2^99

__device__ __forceinline__ void cpasync4(uint32_t saddr, const float* g) {
    asm volatile("cp.async.ca.shared.global [%0], [%1], 4;"
                 :: "r"(saddr), "l"(g) : "memory");
}
__device__ __forceinline__ void cpcommit() {
    asm volatile("cp.async.commit_group;" ::: "memory");
}
template <int N> __device__ __forceinline__ void cpwait() {
    asm volatile("cp.async.wait_group %0;" :: "n"(N) : "memory");
}

__device__ __forceinline__ float pick5(const float a0, const float a1, const float a2,
                                       const float a3, const float a4, int j) {
    float r = a0;
    if (j == 1) r = a1;
    else if (j == 2) r = a2;
    else if (j == 3) r = a3;
    else if (j == 4) r = a4;
    return r;
}

__global__ __launch_bounds__(32, 1)
void ctc_fused_kernel(const int* __restrict__ y_true,
                      const float* __restrict__ y_pred,
                      const int* __restrict__ input_length,
                      const int* __restrict__ label_length,
                      float* __restrict__ out)
{
    __shared__ float ring[DEPTH][RSTRIDE];

    const int b    = blockIdx.x;
    const int lane = threadIdx.x;
    const unsigned FULL = 0xffffffffu;

    const int Tb = input_length[b];          // warp-uniform, in [256, 512]
    const int Ll = label_length[b];
    const int Sb = 2 * Ll + 1;

    const int*   lrow = y_true + b * LL;
    const float* prow = y_pred + (size_t)b * TT * CC;

    // Per-lane gather sources: label classes lane and lane+32; lane 0 blank.
    const float* gbase0 = prow + lrow[lane];
    const float* gbase1 = prow + lrow[lane + 32];
    const float* gblank = prow + BLANKC;

    const uint32_t smem_base = (uint32_t)__cvta_generic_to_shared(&ring[0][0]);

    // Zero the sink slot (65) of every ring row once; cp.async never writes it.
    for (int r = lane; r < DEPTH; r += 32) ring[r][65] = 0.0f;

    // Per-lane static state metadata: states s = lane*5 + j
    int   off[JPER];     // compact-row index: s>>1 (label), 64 (blank), 65 (zero sink)
    float skipf[JPER];
#pragma unroll
    for (int j = 0; j < JPER; j++) {
        const int s = lane * JPER + j;
        const bool v = (s < SS) && (s < Sb);
        int  o  = 65;                        // zero sink for invalid states
        bool sk = false;
        if (v) {
            if (s & 1) {
                o = s >> 1;
                if (s >= 3) sk = (lrow[o] != lrow[o - 1]);
            } else {
                o = 64;                      // blank
            }
        }
        off[j]   = o;
        skipf[j] = sk ? 1.0f : 0.0f;
    }

#define FETCH_ROW(r_) do {                                                          \
        const int r__ = (r_);                                                       \
        const uint32_t wa__ = smem_base + (uint32_t)(((r__) & (DEPTH-1)) * RSTRIDE + lane) * 4u; \
        cpasync4(wa__, gbase0 + (size_t)r__ * CC);                                  \
        cpasync4(wa__ + 128u, gbase1 + (size_t)r__ * CC);                           \
        if (lane == 0)                                                              \
            cpasync4(smem_base + (uint32_t)(((r__) & (DEPTH-1)) * RSTRIDE + 64) * 4u, \
                     gblank + (size_t)r__ * CC);                                    \
    } while (0)

    // ---- prologue: rows 0..DEPTH-1 (Tb >= 256 > DEPTH), one commit per 2 rows ----
#pragma unroll
    for (int g = 0; g < DEPTH / 2; g++) {
        FETCH_ROW(2 * g);
        FETCH_ROW(2 * g + 1);
        cpcommit();
    }
    cpwait<31>();                            // group 0 complete -> rows 0,1 resident

    // alpha init: linear domain, mass 1 at s=0
    float a0 = 0.f, a1r = 0.f, a2r = 0.f, a3r = 0.f, a4r = 0.f;
    if (lane == 0) a0 = 1.0f;

    // ee[parity][j]: emissions (p + EPS) for current / next step
    float ee[2][JPER];
#pragma unroll
    for (int j = 0; j < JPER; j++) ee[0][j] = ring[0][off[j]] + EPSF;

    int esum = 0;   // exact power-of-two rescale accumulator
                    // invariant: alpha_true = alpha_stored * 2^esum

    for (int tb = 0; tb < Tb; tb += 4) {
#pragma unroll
        for (int k = 0; k < 4; k++) {
            const int t   = tb + k;
            const int cur = t & 1;
            const int nxt = cur ^ 1;

            // Prefetch 2 rows + commit + wait every other step (t even since tb%4==0).
            // Only rows < Tb are fetched; empty commits keep the group counter
            // advancing so wait<31> keeps covering the consumer's window.
            if ((k & 1) == 0) {
                const int tp = t + DEPTH;
                if (tp < Tb)     FETCH_ROW(tp);
                if (tp + 1 < Tb) FETCH_ROW(tp + 1);
                cpcommit();
                cpwait<31>();    // completion through rows t+3
            }

            // Read raw emissions for step t+1 (slot content only meaningful
            // for rows < Tb; the final read past Tb-1 feeds an unused ee).
            const int tn = (t + 1 < TT) ? (t + 1) : (TT - 1);
            const float* rr = &ring[tn & (DEPTH - 1)][0];
            const float r0 = rr[off[0]], r1 = rr[off[1]], r2 = rr[off[2]],
                        r3 = rr[off[3]], r4 = rr[off[4]];

            // alpha recurrence for step t (critical path: shfl + 3 flops)
            if (t < Tb) {
                float h3 = __shfl_up_sync(FULL, a3r, 1);
                float h4 = __shfl_up_sync(FULL, a4r, 1);
                if (lane == 0) { h3 = 0.f; h4 = 0.f; }

                const float n0 = (a0  + h4  + skipf[0] * h3 ) * ee[cur][0];
                const float n1 = (a1r + a0  + skipf[1] * h4 ) * ee[cur][1];
                const float n2 = (a2r + a1r + skipf[2] * a0 ) * ee[cur][2];
                const float n3 = (a3r + a2r + skipf[3] * a1r) * ee[cur][3];
                const float n4 = (a4r + a3r + skipf[4] * a2r) * ee[cur][4];
                a0 = n0; a1r = n1; a2r = n2; a3r = n3; a4r = n4;
            }

            // build emissions for step t+1 (sink slot is 0 -> ee=EPS, decays)
            ee[nxt][0] = r0 + EPSF;
            ee[nxt][1] = r1 + EPSF;
            ee[nxt][2] = r2 + EPSF;
            ee[nxt][3] = r3 + EPSF;
            ee[nxt][4] = r4 + EPSF;

            // exact power-of-two rescale every 4 steps, anchored near 2^99
            if (k == 3 && t < Tb) {
                float m = fmaxf(fmaxf(fmaxf(a0, a1r), fmaxf(a2r, a3r)), a4r);
                unsigned mu = __reduce_max_sync(FULL, __float_as_uint(m));
                if (mu != 0u) {
                    const int ef = (int)(mu >> 23);
                    int kk = EF_TARGET - ef;
                    kk = kk > 127 ? 127 : (kk < -126 ? -126 : kk);
                    const float sc = __int_as_float((unsigned)(127 + kk) << 23); // 2^kk
                    esum -= kk;
                    a0 *= sc; a1r *= sc; a2r *= sc; a3r *= sc; a4r *= sc;
                }
            }
        }
    }
#undef FETCH_ROW

    // loss = -( log(alpha[2Ll] + alpha[2Ll-1]) + esum*ln2 )
    const int se0 = 2 * Ll;
    const int se1 = 2 * Ll - 1;
    const int l0 = se0 / JPER, j0 = se0 % JPER;
    const int l1 = se1 / JPER, j1 = se1 % JPER;

    const float v0 = pick5(a0, a1r, a2r, a3r, a4r, j0);
    const float v1 = pick5(a0, a1r, a2r, a3r, a4r, j1);
    const float fa1 = __shfl_sync(FULL, v0, l0);
    const float fa2 = __shfl_sync(FULL, v1, l1);

    if (lane == 0) {
        const float s = fmaxf(fa1 + fa2, 1e-43f);
        out[b] = -(logf(s) + (float)esum * 0.6931471805599453f);
    }

    cpwait<0>();   // drain any stragglers before exit
}

extern "C" void kernel_launch(void* const* d_in, const int* in_sizes, int n_in,
                              void* d_out, int out_size)
{
    const int*   y_true       = (const int*)  d_in[0];   // [B,L] int32
    const float* y_pred       = (const float*)d_in[1];   // [B,T,C] f32
    const int*   input_length = (const int*)  d_in[2];   // [B,1] int32
    const int*   label_length = (const int*)  d_in[3];   // [B,1] int32
    float*       out          = (float*)d_out;           // [B,1] f32

    ctc_fused_kernel<<<BQ, 32>>>(y_true, y_pred, input_length, label_length, out);
}

// round 10
// speedup vs baseline: 1.0871x; 1.0871x over previous
#include <cuda_runtime.h>
#include <cstdint>

// Problem constants (fixed by the dataset)
#define BQ    128
#define TT    512
#define CC    1024
#define LL    64
#define SS    129           // 2*LL + 1 extended states
#define BLANKC 1023
#define EPSF  1e-7f
#define JPER  5             // states per lane (26 lanes * 5 = 130 >= 129)
#define DEPTH 64            // smem ring rows (power of two)
#define RSTRIDE 68          // ring row stride in floats (66 used)
#define EF_TARGET 226       // rescale anchor: warp max near 2^99
#define NPROD 4             // producer warps
#define PD    7             // per-producer pending commit groups (wait_group<7>)
#define LEAD  (DEPTH - 8)   // producer may run this many rows ahead of consumer

__device__ __forceinline__ void cpasync4(uint32_t saddr, const float* g) {
    asm volatile("cp.async.ca.shared.global [%0], [%1], 4;"
                 :: "r"(saddr), "l"(g) : "memory");
}
__device__ __forceinline__ void cpcommit() {
    asm volatile("cp.async.commit_group;" ::: "memory");
}
template <int N> __device__ __forceinline__ void cpwait() {
    asm volatile("cp.async.wait_group %0;" :: "n"(N) : "memory");
}

__device__ __forceinline__ float pick5(const float a0, const float a1, const float a2,
                                       const float a3, const float a4, int j) {
    float r = a0;
    if (j == 1) r = a1;
    else if (j == 2) r = a2;
    else if (j == 3) r = a3;
    else if (j == 4) r = a4;
    return r;
}

__global__ __launch_bounds__(32 * (NPROD + 1), 1)
void ctc_mp_kernel(const int* __restrict__ y_true,
                   const float* __restrict__ y_pred,
                   const int* __restrict__ input_length,
                   const int* __restrict__ label_length,
                   float* __restrict__ out)
{
    __shared__ float ring[DEPTH][RSTRIDE];
    __shared__ volatile int s_ready[NPROD];  // highest completed row per producer
    __shared__ volatile int s_cons;          // rows <= s_cons are dead (consumer done)

    const int b    = blockIdx.x;
    const int tid  = threadIdx.x;
    const int warp = tid >> 5;
    const int lane = tid & 31;
    const unsigned FULL = 0xffffffffu;

    const int Tb = input_length[b];          // block-uniform, in [256, 512]
    const int Ll = label_length[b];
    const int Sb = 2 * Ll + 1;

    const int*   lrow = y_true + b * LL;
    const float* prow = y_pred + (size_t)b * TT * CC;
    const uint32_t smem_base = (uint32_t)__cvta_generic_to_shared(&ring[0][0]);

    if (tid == 0) {
        s_cons = 0;
#pragma unroll
        for (int p = 0; p < NPROD; p++) s_ready[p] = -1;
    }
    // Consumer-only sink slot: zero once (cp.async never writes slot 65).
    if (warp == 0) {
        for (int r = lane; r < DEPTH; r += 32) ring[r][65] = 0.0f;
    }
    __syncthreads();   // flags + sinks visible before anyone polls / fetches

    if (warp >= 1) {
        // ========================= PRODUCER p =========================
        const int p = warp - 1;
        const float* gbase0 = prow + lrow[lane];
        const float* gbase1 = prow + lrow[lane + 32];
        const float* gblank = prow + BLANKC;

        int i = 0;
        for (int r = p; r < Tb; r += NPROD, i++) {
            // backpressure: stay within LEAD rows of consumer progress
            int c;
            do {
                c = (lane == 0) ? s_cons : 0;
                c = __shfl_sync(FULL, c, 0);
            } while (r >= c + LEAD);

            const uint32_t wa = smem_base
                + (uint32_t)((r & (DEPTH - 1)) * RSTRIDE + lane) * 4u;
            cpasync4(wa, gbase0 + (size_t)r * CC);
            cpasync4(wa + 128u, gbase1 + (size_t)r * CC);
            if (lane == 0)
                cpasync4(smem_base + (uint32_t)((r & (DEPTH - 1)) * RSTRIDE + 64) * 4u,
                         gblank + (size_t)r * CC);
            cpcommit();

            cpwait<PD>();                     // no-op until PD+1 groups pending
            if (i >= PD) {
                __threadfence_block();        // ring data before flag
                if (lane == 0) s_ready[p] = p + NPROD * (i - PD);
            }
        }
        cpwait<0>();
        __threadfence_block();
        if (lane == 0) s_ready[p] = 0x3fffffff;   // all my rows complete
    } else {
        // ========================= CONSUMER =========================
        // Per-lane static state metadata: states s = lane*5 + j
        int   off[JPER];   // 0..63 label, 64 blank, 65 zero sink (invalid)
        float skipf[JPER];
#pragma unroll
        for (int j = 0; j < JPER; j++) {
            const int s = lane * JPER + j;
            const bool v = (s < SS) && (s < Sb);
            int  o  = 65;
            bool sk = false;
            if (v) {
                if (s & 1) {
                    o = s >> 1;
                    if (s >= 3) sk = (lrow[o] != lrow[o - 1]);
                } else {
                    o = 64;
                }
            }
            off[j]   = o;
            skipf[j] = sk ? 1.0f : 0.0f;
        }

        float a0 = 0.f, a1r = 0.f, a2r = 0.f, a3r = 0.f, a4r = 0.f;
        if (lane == 0) a0 = 1.0f;

        // wait for rows 0..4 (all lanes poll the same 4 words: broadcast LDS)
        {
            int m;
            do {
                m = min(min(s_ready[0], s_ready[1]), min(s_ready[2], s_ready[3]));
            } while (m < 4);
        }

        float ee[2][JPER];
#pragma unroll
        for (int j = 0; j < JPER; j++) ee[0][j] = ring[0][off[j]] + EPSF;

        int esum = 0;    // exact power-of-two rescale accumulator

        const int NG = (Tb + 3) >> 2;        // 4-step groups
        for (int i = 0; i < NG; i++) {
            // ensure rows up to 4i+4 (capped at Tb-1) are resident
            {
                int tgt = 4 * i + 4;
                if (tgt > Tb - 1) tgt = Tb - 1;
                int m;
                do {
                    m = min(min(s_ready[0], s_ready[1]), min(s_ready[2], s_ready[3]));
                } while (m < tgt);
            }

#pragma unroll
            for (int k = 0; k < 4; k++) {
                const int t   = 4 * i + k;
                const int cur = t & 1;
                const int nxt = cur ^ 1;

                // raw emissions for step t+1 (row clamp: final read may be a
                // dead slot; its ee feeds a step that is never computed)
                const int tn = (t + 1 < TT) ? (t + 1) : (TT - 1);
                const float* rr = &ring[tn & (DEPTH - 1)][0];
                const float r0 = rr[off[0]], r1 = rr[off[1]], r2 = rr[off[2]],
                            r3 = rr[off[3]], r4 = rr[off[4]];

                if (t < Tb) {
                    float h3 = __shfl_up_sync(FULL, a3r, 1);
                    float h4 = __shfl_up_sync(FULL, a4r, 1);
                    if (lane == 0) { h3 = 0.f; h4 = 0.f; }

                    const float n0 = (a0  + h4  + skipf[0] * h3 ) * ee[cur][0];
                    const float n1 = (a1r + a0  + skipf[1] * h4 ) * ee[cur][1];
                    const float n2 = (a2r + a1r + skipf[2] * a0 ) * ee[cur][2];
                    const float n3 = (a3r + a2r + skipf[3] * a1r) * ee[cur][3];
                    const float n4 = (a4r + a3r + skipf[4] * a2r) * ee[cur][4];
                    a0 = n0; a1r = n1; a2r = n2; a3r = n3; a4r = n4;
                }

                ee[nxt][0] = r0 + EPSF;
                ee[nxt][1] = r1 + EPSF;
                ee[nxt][2] = r2 + EPSF;
                ee[nxt][3] = r3 + EPSF;
                ee[nxt][4] = r4 + EPSF;

                // exact power-of-two rescale every 4 steps (anchor ~2^99)
                if (k == 3 && t < Tb) {
                    float m = fmaxf(fmaxf(fmaxf(a0, a1r), fmaxf(a2r, a3r)), a4r);
                    unsigned mu = __reduce_max_sync(FULL, __float_as_uint(m));
                    if (mu != 0u) {
                        const int ef = (int)(mu >> 23);
                        int kk = EF_TARGET - ef;
                        kk = kk > 127 ? 127 : (kk < -126 ? -126 : kk);
                        const float sc = __int_as_float((unsigned)(127 + kk) << 23);
                        esum -= kk;
                        a0 *= sc; a1r *= sc; a2r *= sc; a3r *= sc; a4r *= sc;
                    }
                }
            }

            // rows <= 4i+4 are dead now (their values live in ee registers)
            if (lane == 0) s_cons = 4 * i + 4;
        }

        // loss = -( log(alpha[2Ll] + alpha[2Ll-1]) + esum*ln2 )
        const int se0 = 2 * Ll;
        const int se1 = 2 * Ll - 1;
        const int l0 = se0 / JPER, j0 = se0 % JPER;
        const int l1 = se1 / JPER, j1 = se1 % JPER;

        const float v0 = pick5(a0, a1r, a2r, a3r, a4r, j0);
        const float v1 = pick5(a0, a1r, a2r, a3r, a4r, j1);
        const float fa1 = __shfl_sync(FULL, v0, l0);
        const float fa2 = __shfl_sync(FULL, v1, l1);

        if (lane == 0) {
            const float s = fmaxf(fa1 + fa2, 1e-43f);
            out[b] = -(logf(s) + (float)esum * 0.6931471805599453f);
            s_cons = 0x3fffffff;             // release any producer stragglers
        }
    }
}

extern "C" void kernel_launch(void* const* d_in, const int* in_sizes, int n_in,
                              void* d_out, int out_size)
{
    const int*   y_true       = (const int*)  d_in[0];   // [B,L] int32
    const float* y_pred       = (const float*)d_in[1];   // [B,T,C] f32
    const int*   input_length = (const int*)  d_in[2];   // [B,1] int32
    const int*   label_length = (const int*)  d_in[3];   // [B,1] int32
    float*       out          = (float*)d_out;           // [B,1] f32

    ctc_mp_kernel<<<BQ, 32 * (NPROD + 1)>>>(y_true, y_pred,
                                            input_length, label_length, out);
}